// round 1
// baseline (speedup 1.0000x reference)
#include <cuda_runtime.h>

#define NI 128
#define NC 128
#define RR 36
#define WW 32
#define DD 1024

// Scratch (allocation-free contract: __device__ globals)
__device__ float g_sim[(size_t)NC * NI * RR * WW];   // [c][i][r][w]  (75.5 MB)
__device__ float g_gimg[(size_t)NI * RR * RR];       // per-image region Gram
__device__ float g_gcap[(size_t)NC * WW * WW];       // per-caption word Gram

// ---------- packed f32x2 helpers ----------
__device__ __forceinline__ unsigned long long pk2(float lo, float hi) {
    unsigned long long r;
    asm("mov.b64 %0, {%1, %2};" : "=l"(r) : "f"(lo), "f"(hi));
    return r;
}
__device__ __forceinline__ void fma2(unsigned long long &c, unsigned long long a, unsigned long long b) {
    asm("fma.rn.f32x2 %0, %1, %2, %0;" : "+l"(c) : "l"(a), "l"(b));
}
__device__ __forceinline__ float2 up2(unsigned long long v) {
    float2 f;
    asm("mov.b64 {%0, %1}, %2;" : "=f"(f.x), "=f"(f.y) : "l"(v));
    return f;
}

// ---------- warp reductions ----------
__device__ __forceinline__ float wsum(float v) {
    #pragma unroll
    for (int o = 16; o; o >>= 1) v += __shfl_xor_sync(0xffffffffu, v, o);
    return v;
}
__device__ __forceinline__ float wmax(float v) {
    #pragma unroll
    for (int o = 16; o; o >>= 1) v = fmaxf(v, __shfl_xor_sync(0xffffffffu, v, o));
    return v;
}

// ============================================================
// Kernel 1: similarity GEMM  S = images(4608,1024) @ captions(4096,1024)^T
// Output written in pair-major layout g_sim[c][i][r][w].
// BM=BN=128, BK=16, 256 threads, 8x8 microtile, f32x2 packed FMA.
// ============================================================
#define GBK 16
__global__ __launch_bounds__(256, 2) void gemm_kernel(
    const float* __restrict__ A,   // images  (4608,1024)
    const float* __restrict__ B)   // captions(4096,1024)
{
    __shared__ float As[GBK][128];
    __shared__ float Bs[GBK][128];

    const int tid = threadIdx.x;
    const int tx = tid & 15, ty = tid >> 4;
    const int bm0 = blockIdx.y * 128;
    const int bn0 = blockIdx.x * 128;

    unsigned long long c2[8][4];
    #pragma unroll
    for (int m = 0; m < 8; m++)
        #pragma unroll
        for (int j = 0; j < 4; j++) c2[m][j] = 0ull;

    // two float4 loads per operand per tile
    const int f0 = tid, f1 = tid + 256;
    const int ra0 = f0 >> 2, kq0 = f0 & 3;
    const int ra1 = f1 >> 2, kq1 = f1 & 3;
    const float4* Ar0 = (const float4*)(A + (size_t)(bm0 + ra0) * DD);
    const float4* Ar1 = (const float4*)(A + (size_t)(bm0 + ra1) * DD);
    const float4* Br0 = (const float4*)(B + (size_t)(bn0 + ra0) * DD);
    const float4* Br1 = (const float4*)(B + (size_t)(bn0 + ra1) * DD);

    // preload tile 0
    float4 pa0 = Ar0[kq0], pa1 = Ar1[kq1], pb0 = Br0[kq0], pb1 = Br1[kq1];
    As[kq0*4+0][ra0]=pa0.x; As[kq0*4+1][ra0]=pa0.y; As[kq0*4+2][ra0]=pa0.z; As[kq0*4+3][ra0]=pa0.w;
    As[kq1*4+0][ra1]=pa1.x; As[kq1*4+1][ra1]=pa1.y; As[kq1*4+2][ra1]=pa1.z; As[kq1*4+3][ra1]=pa1.w;
    Bs[kq0*4+0][ra0]=pb0.x; Bs[kq0*4+1][ra0]=pb0.y; Bs[kq0*4+2][ra0]=pb0.z; Bs[kq0*4+3][ra0]=pb0.w;
    Bs[kq1*4+0][ra1]=pb1.x; Bs[kq1*4+1][ra1]=pb1.y; Bs[kq1*4+2][ra1]=pb1.z; Bs[kq1*4+3][ra1]=pb1.w;
    __syncthreads();

    const int NT = DD / GBK;  // 64 tiles
    for (int kt = 0; kt < NT; kt++) {
        float4 na0, na1, nb0, nb1;
        if (kt + 1 < NT) {
            int base = (kt + 1) * 4;
            na0 = Ar0[base + kq0]; na1 = Ar1[base + kq1];
            nb0 = Br0[base + kq0]; nb1 = Br1[base + kq1];
        }
        #pragma unroll
        for (int k = 0; k < GBK; k++) {
            float4 av0 = *(const float4*)&As[k][ty * 8];
            float4 av1 = *(const float4*)&As[k][ty * 8 + 4];
            float4 bv0 = *(const float4*)&Bs[k][tx * 8];
            float4 bv1 = *(const float4*)&Bs[k][tx * 8 + 4];
            unsigned long long b2[4];
            b2[0] = pk2(bv0.x, bv0.y); b2[1] = pk2(bv0.z, bv0.w);
            b2[2] = pk2(bv1.x, bv1.y); b2[3] = pk2(bv1.z, bv1.w);
            float am[8] = {av0.x, av0.y, av0.z, av0.w, av1.x, av1.y, av1.z, av1.w};
            #pragma unroll
            for (int m = 0; m < 8; m++) {
                unsigned long long a2 = pk2(am[m], am[m]);
                fma2(c2[m][0], a2, b2[0]);
                fma2(c2[m][1], a2, b2[1]);
                fma2(c2[m][2], a2, b2[2]);
                fma2(c2[m][3], a2, b2[3]);
            }
        }
        __syncthreads();
        if (kt + 1 < NT) {
            As[kq0*4+0][ra0]=na0.x; As[kq0*4+1][ra0]=na0.y; As[kq0*4+2][ra0]=na0.z; As[kq0*4+3][ra0]=na0.w;
            As[kq1*4+0][ra1]=na1.x; As[kq1*4+1][ra1]=na1.y; As[kq1*4+2][ra1]=na1.z; As[kq1*4+3][ra1]=na1.w;
            Bs[kq0*4+0][ra0]=nb0.x; Bs[kq0*4+1][ra0]=nb0.y; Bs[kq0*4+2][ra0]=nb0.z; Bs[kq0*4+3][ra0]=nb0.w;
            Bs[kq1*4+0][ra1]=nb1.x; Bs[kq1*4+1][ra1]=nb1.y; Bs[kq1*4+2][ra1]=nb1.z; Bs[kq1*4+3][ra1]=nb1.w;
            __syncthreads();
        }
    }

    // epilogue: row m = i*36+r, col n = c*32+w  ->  g_sim[c*147456 + m*32 + w]
    const int nb = bn0 + tx * 8;
    const int cblk = nb >> 5;
    const int wb = nb & 31;
    #pragma unroll
    for (int m = 0; m < 8; m++) {
        int row = bm0 + ty * 8 + m;
        size_t base = (size_t)cblk * 147456 + (size_t)row * 32 + wb;
        #pragma unroll
        for (int j = 0; j < 4; j++) {
            float2 v = up2(c2[m][j]);
            *(float2*)(g_sim + base + 2 * j) = v;
        }
    }
}

// ============================================================
// Kernel 2: per-image 36x36 region Gram
// ============================================================
__global__ __launch_bounds__(256) void gram_img_kernel(const float* __restrict__ X) {
    __shared__ float Xs[36 * 132];
    const int i = blockIdx.x, tid = threadIdx.x;
    float acc[3][3];
    #pragma unroll
    for (int a = 0; a < 3; a++)
        #pragma unroll
        for (int b = 0; b < 3; b++) acc[a][b] = 0.f;
    const int r0 = (tid / 12) * 3, c0 = (tid % 12) * 3;
    const bool act = tid < 144;
    const float* base = X + (size_t)i * RR * DD;
    for (int ch = 0; ch < 8; ch++) {
        for (int f = tid; f < 1152; f += 256) {
            int row = f >> 5, q = f & 31;
            float4 v = *(const float4*)(base + (size_t)row * DD + ch * 128 + q * 4);
            *(float4*)&Xs[row * 132 + q * 4] = v;
        }
        __syncthreads();
        if (act) {
            for (int d = 0; d < 128; d++) {
                float x0 = Xs[(r0+0)*132+d], x1 = Xs[(r0+1)*132+d], x2 = Xs[(r0+2)*132+d];
                float y0 = Xs[(c0+0)*132+d], y1 = Xs[(c0+1)*132+d], y2 = Xs[(c0+2)*132+d];
                acc[0][0] += x0*y0; acc[0][1] += x0*y1; acc[0][2] += x0*y2;
                acc[1][0] += x1*y0; acc[1][1] += x1*y1; acc[1][2] += x1*y2;
                acc[2][0] += x2*y0; acc[2][1] += x2*y1; acc[2][2] += x2*y2;
            }
        }
        __syncthreads();
    }
    if (act) {
        float* gp = g_gimg + (size_t)i * (RR * RR);
        #pragma unroll
        for (int a = 0; a < 3; a++)
            #pragma unroll
            for (int b = 0; b < 3; b++)
                gp[(r0 + a) * RR + (c0 + b)] = acc[a][b];
    }
}

// ============================================================
// Kernel 3: per-caption 32x32 word Gram
// ============================================================
__global__ __launch_bounds__(256) void gram_cap_kernel(const float* __restrict__ X) {
    __shared__ float Xs[32 * 132];
    const int c = blockIdx.x, tid = threadIdx.x;
    float acc[4][4];
    #pragma unroll
    for (int a = 0; a < 4; a++)
        #pragma unroll
        for (int b = 0; b < 4; b++) acc[a][b] = 0.f;
    const int r0 = (tid / 8) * 4, c0 = (tid % 8) * 4;
    const bool act = tid < 64;
    const float* base = X + (size_t)c * WW * DD;
    for (int ch = 0; ch < 8; ch++) {
        for (int f = tid; f < 1024; f += 256) {
            int row = f >> 5, q = f & 31;
            float4 v = *(const float4*)(base + (size_t)row * DD + ch * 128 + q * 4);
            *(float4*)&Xs[row * 132 + q * 4] = v;
        }
        __syncthreads();
        if (act) {
            for (int d = 0; d < 128; d++) {
                float x0 = Xs[(r0+0)*132+d], x1 = Xs[(r0+1)*132+d];
                float x2 = Xs[(r0+2)*132+d], x3 = Xs[(r0+3)*132+d];
                float y0 = Xs[(c0+0)*132+d], y1 = Xs[(c0+1)*132+d];
                float y2 = Xs[(c0+2)*132+d], y3 = Xs[(c0+3)*132+d];
                acc[0][0]+=x0*y0; acc[0][1]+=x0*y1; acc[0][2]+=x0*y2; acc[0][3]+=x0*y3;
                acc[1][0]+=x1*y0; acc[1][1]+=x1*y1; acc[1][2]+=x1*y2; acc[1][3]+=x1*y3;
                acc[2][0]+=x2*y0; acc[2][1]+=x2*y1; acc[2][2]+=x2*y2; acc[2][3]+=x2*y3;
                acc[3][0]+=x3*y0; acc[3][1]+=x3*y1; acc[3][2]+=x3*y2; acc[3][3]+=x3*y3;
            }
        }
        __syncthreads();
    }
    if (act) {
        float* gp = g_gcap + (size_t)c * (WW * WW);
        #pragma unroll
        for (int a = 0; a < 4; a++)
            #pragma unroll
            for (int b = 0; b < 4; b++)
                gp[(r0 + a) * WW + (c0 + b)] = acc[a][b];
    }
}

// ============================================================
// Kernel 4: per-(image,caption) focal attention + cosine
// grid (128 images, 128 captions), 256 threads (8 warps).
// 68 warp tasks: 32 t2i queries (w), 36 i2t queries (r).
// ============================================================
__global__ __launch_bounds__(256) void pair_kernel(float* __restrict__ out) {
    const int i = blockIdx.x, c = blockIdx.y;
    __shared__ float M[36 * 33];    // sim[r][w]
    __shared__ float A1[36 * 33];   // t2i: leaky+rownorm over w, [r][w]
    __shared__ float A2[32 * 37];   // i2t: leaky+norm over r,    [w][r]
    __shared__ float Gi[36 * 37];   // image Gram [r][r']
    __shared__ float Gc[32 * 33];   // caption Gram [w][w']
    __shared__ float At[32 * 37];   // t2i attn scratch [w][r]
    __shared__ float Ai[36 * 33];   // i2t attn scratch [r][w]
    __shared__ float accT, accI;

    const int tid = threadIdx.x;
    if (tid == 0) { accT = 0.f; accI = 0.f; }

    const float* simp = g_sim + ((size_t)c * NI + i) * (RR * WW);
    for (int g = tid; g < RR * WW; g += 256) {
        int r = g >> 5, w = g & 31;
        M[r * 33 + w] = simp[g];
    }
    const float* gip = g_gimg + (size_t)i * (RR * RR);
    for (int g = tid; g < RR * RR; g += 256) {
        int r = g / 36, rr = g % 36;
        Gi[r * 37 + rr] = gip[g];
    }
    const float* gcp = g_gcap + (size_t)c * (WW * WW);
    for (int g = tid; g < WW * WW; g += 256) {
        int w = g >> 5, ww = g & 31;
        Gc[w * 33 + ww] = gcp[g];
    }
    __syncthreads();

    const int wd = tid >> 5, ln = tid & 31;

    // ---- normalize phase: 36 t2i rows + 32 i2t cols ----
    for (int task = wd; task < 68; task += 8) {
        if (task < 36) {
            int r = task;
            float v = M[r * 33 + ln];
            v = v > 0.f ? v : 0.1f * v;
            float nrm = sqrtf(wsum(v * v)) + 1e-8f;
            A1[r * 33 + ln] = v / nrm;
        } else {
            int w = task - 36;
            float v1 = M[ln * 33 + w];
            v1 = v1 > 0.f ? v1 : 0.1f * v1;
            float v2 = 0.f;
            if (ln < 4) {
                v2 = M[(ln + 32) * 33 + w];
                v2 = v2 > 0.f ? v2 : 0.1f * v2;
            }
            float nrm = sqrtf(wsum(v1 * v1 + v2 * v2)) + 1e-8f;
            A2[w * 37 + ln] = v1 / nrm;
            if (ln < 4) A2[w * 37 + ln + 32] = v2 / nrm;
        }
    }
    __syncthreads();

    // ---- attention phase ----
    for (int task = wd; task < 68; task += 8) {
        if (task < 32) {
            // t2i, query word w: softmax over 36 regions
            int w = task;
            int r1 = ln, r2 = ln + 32;
            bool has2 = ln < 4;
            float v1 = A1[r1 * 33 + w];
            float v2 = has2 ? A1[r2 * 33 + w] : 0.f;
            float x1 = 20.f * v1;
            float x2 = has2 ? 20.f * v2 : -1e30f;
            float mx = wmax(fmaxf(x1, x2));
            float e1 = __expf(x1 - mx);
            float e2 = has2 ? __expf(x2 - mx) : 0.f;
            float s = wsum(e1 + e2);
            float p1 = e1 / s, p2 = e2 / s;
            bool m1 = (p1 * 36.f - 1.f) > 0.f;
            bool m2 = has2 && ((p2 * 36.f - 1.f) > 0.f);
            float t = wsum((m1 ? p1 : 0.f) + (m2 ? p2 : 0.f));
            float at1 = m1 ? p1 / t : 0.f;
            float at2 = m2 ? p2 / t : 0.f;
            float num = wsum(at1 * M[r1 * 33 + w] + (has2 ? at2 * M[r2 * 33 + w] : 0.f));
            At[w * 37 + r1] = at1;
            if (has2) At[w * 37 + r2] = at2;
            __syncwarp();
            float in1 = 0.f, in2 = 0.f;
            const float* atp = &At[w * 37];
            #pragma unroll 4
            for (int rr = 0; rr < 36; rr++) {
                float a = atp[rr];
                in1 = fmaf(Gi[r1 * 37 + rr], a, in1);
                if (has2) in2 = fmaf(Gi[r2 * 37 + rr], a, in2);
            }
            float d2 = wsum(at1 * in1 + at2 * in2);
            float den = fmaxf(sqrtf(d2), 1e-8f);
            float ncap = fmaxf(sqrtf(Gc[w * 33 + w]), 1e-8f);
            float cs = num / (ncap * den);
            if (ln == 0) atomicAdd(&accT, cs);
        } else {
            // i2t, query region r: softmax over 32 words
            int r = task - 32;
            float v = A2[ln * 37 + r];
            float x = 20.f * v;
            float mx = wmax(x);
            float e = __expf(x - mx);
            float s = wsum(e);
            float p = e / s;
            bool mk = (p * 32.f - 1.f) > 0.f;
            float t = wsum(mk ? p : 0.f);
            float at = mk ? p / t : 0.f;
            float num = wsum(at * M[r * 33 + ln]);
            Ai[r * 33 + ln] = at;
            __syncwarp();
            float inn = 0.f;
            const float* aip = &Ai[r * 33];
            #pragma unroll 4
            for (int ww2 = 0; ww2 < 32; ww2++) {
                inn = fmaf(Gc[ln * 33 + ww2], aip[ww2], inn);
            }
            float d2 = wsum(at * inn);
            float den = fmaxf(sqrtf(d2), 1e-8f);
            float nim = fmaxf(sqrtf(Gi[r * 37 + r]), 1e-8f);
            float cs = num / (nim * den);
            if (ln == 0) atomicAdd(&accI, cs);
        }
    }
    __syncthreads();
    if (tid == 0) out[(size_t)i * NC + c] = accT * (1.f / 32.f) + accI * (1.f / 36.f);
}

// ============================================================
extern "C" void kernel_launch(void* const* d_in, const int* in_sizes, int n_in,
                              void* d_out, int out_size) {
    const float* images   = (const float*)d_in[0];
    const float* captions = (const float*)d_in[1];
    float* out = (float*)d_out;

    gemm_kernel<<<dim3(32, 36), 256>>>(images, captions);
    gram_img_kernel<<<128, 256>>>(images);
    gram_cap_kernel<<<128, 256>>>(captions);
    pair_kernel<<<dim3(128, 128), 256>>>(out);
}

// round 3
// speedup vs baseline: 1.6066x; 1.6066x over previous
#include <cuda_runtime.h>
#include <cuda_bf16.h>
#include <cstdint>

#define NI 128
#define NC 128
#define RR 36
#define WW 32
#define DD 1024
#define MROWS (NI*RR)   // 4608
#define NCOLS (NC*WW)   // 4096

// Scratch (allocation-free contract: __device__ globals)
__device__ float g_sim[(size_t)NC * NI * RR * WW];   // [c][i][r][w]
__device__ float g_gimg[(size_t)NI * RR * RR];
__device__ float g_gcap[(size_t)NC * WW * WW];
__device__ __nv_bfloat16 g_ahi[(size_t)MROWS * DD];
__device__ __nv_bfloat16 g_alo[(size_t)MROWS * DD];
__device__ __nv_bfloat16 g_bhi[(size_t)NCOLS * DD];
__device__ __nv_bfloat16 g_blo[(size_t)NCOLS * DD];

// ---------------- helpers ----------------
__device__ __forceinline__ uint32_t smem_u32(const void* p) {
    uint32_t a;
    asm("{ .reg .u64 t; cvta.to.shared.u64 t, %1; cvt.u32.u64 %0, t; }" : "=r"(a) : "l"(p));
    return a;
}
__device__ __forceinline__ uint32_t swz128(uint32_t off) { return off ^ ((off >> 3) & 0x70); }

__device__ __forceinline__ void ldsm_x4(uint32_t* r, uint32_t addr) {
    asm volatile("ldmatrix.sync.aligned.m8n8.x4.shared.b16 {%0,%1,%2,%3}, [%4];"
                 : "=r"(r[0]), "=r"(r[1]), "=r"(r[2]), "=r"(r[3]) : "r"(addr));
}
__device__ __forceinline__ void mma16816(float* d, const uint32_t* a, const uint32_t* b) {
    asm volatile(
        "mma.sync.aligned.m16n8k16.row.col.f32.bf16.bf16.f32 "
        "{%0,%1,%2,%3}, {%4,%5,%6,%7}, {%8,%9}, {%0,%1,%2,%3};"
        : "+f"(d[0]), "+f"(d[1]), "+f"(d[2]), "+f"(d[3])
        : "r"(a[0]), "r"(a[1]), "r"(a[2]), "r"(a[3]), "r"(b[0]), "r"(b[1]));
}
__device__ __forceinline__ void cp16(uint32_t saddr, const void* gaddr) {
    asm volatile("cp.async.cg.shared.global [%0], [%1], 16;" :: "r"(saddr), "l"(gaddr));
}

// ---------- warp reductions ----------
__device__ __forceinline__ float wsum(float v) {
    #pragma unroll
    for (int o = 16; o; o >>= 1) v += __shfl_xor_sync(0xffffffffu, v, o);
    return v;
}
__device__ __forceinline__ float wmax(float v) {
    #pragma unroll
    for (int o = 16; o; o >>= 1) v = fmaxf(v, __shfl_xor_sync(0xffffffffu, v, o));
    return v;
}

// ============================================================
// Kernel 0: fp32 -> bf16 hi/lo split
// ============================================================
__global__ __launch_bounds__(256) void convert_kernel(
    const float* __restrict__ A, const float* __restrict__ B)
{
    const size_t NA4 = (size_t)MROWS * DD / 4;
    const size_t NB4 = (size_t)NCOLS * DD / 4;
    size_t t = (size_t)blockIdx.x * 256 + threadIdx.x;
    const float* src;
    __nv_bfloat16 *hi, *lo;
    size_t idx4;
    if (t < NA4)            { src = A; hi = g_ahi; lo = g_alo; idx4 = t; }
    else if (t < NA4 + NB4) { src = B; hi = g_bhi; lo = g_blo; idx4 = t - NA4; }
    else return;
    float4 v = ((const float4*)src)[idx4];
    __nv_bfloat16 h0 = __float2bfloat16_rn(v.x);
    __nv_bfloat16 h1 = __float2bfloat16_rn(v.y);
    __nv_bfloat16 h2 = __float2bfloat16_rn(v.z);
    __nv_bfloat16 h3 = __float2bfloat16_rn(v.w);
    __nv_bfloat16 l0 = __float2bfloat16_rn(v.x - __bfloat162float(h0));
    __nv_bfloat16 l1 = __float2bfloat16_rn(v.y - __bfloat162float(h1));
    __nv_bfloat16 l2 = __float2bfloat16_rn(v.z - __bfloat162float(h2));
    __nv_bfloat16 l3 = __float2bfloat16_rn(v.w - __bfloat162float(h3));
    __nv_bfloat162* hp = (__nv_bfloat162*)(hi + 4 * idx4);
    __nv_bfloat162* lp = (__nv_bfloat162*)(lo + 4 * idx4);
    hp[0] = __nv_bfloat162(h0, h1); hp[1] = __nv_bfloat162(h2, h3);
    lp[0] = __nv_bfloat162(l0, l1); lp[1] = __nv_bfloat162(l2, l3);
}

// ============================================================
// Kernel 1: bf16 mma.sync similarity GEMM, 128x128 tiles, K=1024
// 3-term hi/lo split -> fp32 accum.  cp.async double-buffered.
// ============================================================
#define TILE_B 16384             // 128 rows x 128 bytes (64 bf16)
#define STAGE_B (4 * TILE_B)     // Ahi, Alo, Bhi, Blo
#define NKT 16                   // 1024 / 64

__global__ __launch_bounds__(256, 1) void gemm_mma(void) {
    extern __shared__ char smem[];
    const uint32_t sb = smem_u32(smem);
    const int tid = threadIdx.x;
    const int wid = tid >> 5, ln = tid & 31;
    const int bm0 = blockIdx.y * 128;
    const int bn0 = blockIdx.x * 128;
    const int wm = wid & 3;      // 4 warps along M: 32 rows each
    const int wn = wid >> 2;     // 2 warps along N: 64 cols each

    // staging assignment: tid>>6 selects operand array
    const int which = tid >> 6;
    const int t64 = tid & 63;
    const __nv_bfloat16* gsrc;
    int row0;
    if      (which == 0) { gsrc = g_ahi; row0 = bm0; }
    else if (which == 1) { gsrc = g_alo; row0 = bm0; }
    else if (which == 2) { gsrc = g_bhi; row0 = bn0; }
    else                 { gsrc = g_blo; row0 = bn0; }
    const char* gbase = (const char*)gsrc + (size_t)row0 * (DD * 2);
    const uint32_t sbase_w = sb + which * TILE_B;

    auto issue = [&](int stage, int kt) {
        const char* gp = gbase + (size_t)kt * 128;   // 64 bf16 = 128 B
        const uint32_t sp = sbase_w + stage * STAGE_B;
        #pragma unroll
        for (int j = 0; j < 16; j++) {
            int chunk = t64 + 64 * j;                // 0..1023
            int row = chunk >> 3, cc = chunk & 7;
            cp16(sp + swz128(row * 128 + cc * 16),
                 gp + (size_t)row * (DD * 2) + cc * 16);
        }
        asm volatile("cp.async.commit_group;" ::: "memory");
    };

    float acc[2][8][4];
    #pragma unroll
    for (int am = 0; am < 2; am++)
        #pragma unroll
        for (int na = 0; na < 8; na++)
            #pragma unroll
            for (int q = 0; q < 4; q++) acc[am][na][q] = 0.f;

    issue(0, 0);

    // per-lane ldmatrix address components
    const int a_row = (ln & 7) + ((ln >> 3) & 1) * 8;    // + am*16 + wm*32
    const int a_kb  = (ln >> 4) * 16;                    // + ks*32
    const int b_row = (ln & 7) + (ln >> 4) * 8;          // + p*16 + wn*64
    const int b_kb  = ((ln >> 3) & 1) * 16;              // + ks*32

    #pragma unroll 1
    for (int kt = 0; kt < NKT; kt++) {
        if (kt + 1 < NKT) {
            issue((kt + 1) & 1, kt + 1);
            asm volatile("cp.async.wait_group 1;" ::: "memory");
        } else {
            asm volatile("cp.async.wait_group 0;" ::: "memory");
        }
        __syncthreads();

        const uint32_t st = sb + (kt & 1) * STAGE_B;
        const uint32_t aHi = st, aLo = st + TILE_B;
        const uint32_t bHi = st + 2 * TILE_B, bLo = st + 3 * TILE_B;

        #pragma unroll
        for (int ks = 0; ks < 4; ks++) {
            const int kb = ks * 32;
            uint32_t ah[2][4], al[2][4], bh[8][2], bl[8][2];
            #pragma unroll
            for (int am = 0; am < 2; am++) {
                uint32_t off = swz128((wm * 32 + am * 16 + a_row) * 128 + kb + a_kb);
                ldsm_x4(ah[am], aHi + off);
                ldsm_x4(al[am], aLo + off);
            }
            #pragma unroll
            for (int p = 0; p < 4; p++) {
                uint32_t off = swz128((wn * 64 + p * 16 + b_row) * 128 + kb + b_kb);
                uint32_t r4[4];
                ldsm_x4(r4, bHi + off);
                bh[2*p][0] = r4[0]; bh[2*p][1] = r4[1];
                bh[2*p+1][0] = r4[2]; bh[2*p+1][1] = r4[3];
                ldsm_x4(r4, bLo + off);
                bl[2*p][0] = r4[0]; bl[2*p][1] = r4[1];
                bl[2*p+1][0] = r4[2]; bl[2*p+1][1] = r4[3];
            }
            #pragma unroll
            for (int am = 0; am < 2; am++)
                #pragma unroll
                for (int na = 0; na < 8; na++) {
                    mma16816(acc[am][na], ah[am], bh[na]);
                    mma16816(acc[am][na], ah[am], bl[na]);
                    mma16816(acc[am][na], al[am], bh[na]);
                }
        }
        __syncthreads();
    }

    // epilogue -> g_sim[c][i][r][w]
    const int rq = ln >> 2, cq = (ln & 3) * 2;
    #pragma unroll
    for (int am = 0; am < 2; am++) {
        const int m0 = bm0 + wm * 32 + am * 16 + rq;
        const int m1 = m0 + 8;
        const int i0 = m0 / 36, r0 = m0 - i0 * 36;
        const int i1 = m1 / 36, r1 = m1 - i1 * 36;
        #pragma unroll
        for (int na = 0; na < 8; na++) {
            const int n = bn0 + wn * 64 + na * 8 + cq;
            const int cidx = n >> 5, w = n & 31;
            float* p0 = g_sim + ((size_t)cidx * NI + i0) * (RR * WW) + r0 * WW + w;
            float* p1 = g_sim + ((size_t)cidx * NI + i1) * (RR * WW) + r1 * WW + w;
            float2 v0 = {acc[am][na][0], acc[am][na][1]};
            float2 v1 = {acc[am][na][2], acc[am][na][3]};
            *(float2*)p0 = v0;
            *(float2*)p1 = v1;
        }
    }
}

// ============================================================
// Kernel 2: per-image 36x36 region Gram (fp32 inputs)
// ============================================================
__global__ __launch_bounds__(256) void gram_img_kernel(const float* __restrict__ X) {
    __shared__ float Xs[36 * 132];
    const int i = blockIdx.x, tid = threadIdx.x;
    float acc[3][3];
    #pragma unroll
    for (int a = 0; a < 3; a++)
        #pragma unroll
        for (int b = 0; b < 3; b++) acc[a][b] = 0.f;
    const int r0 = (tid / 12) * 3, c0 = (tid % 12) * 3;
    const bool act = tid < 144;
    const float* base = X + (size_t)i * RR * DD;
    for (int ch = 0; ch < 8; ch++) {
        for (int f = tid; f < 1152; f += 256) {
            int row = f >> 5, q = f & 31;
            float4 v = *(const float4*)(base + (size_t)row * DD + ch * 128 + q * 4);
            *(float4*)&Xs[row * 132 + q * 4] = v;
        }
        __syncthreads();
        if (act) {
            for (int d = 0; d < 128; d++) {
                float x0 = Xs[(r0+0)*132+d], x1 = Xs[(r0+1)*132+d], x2 = Xs[(r0+2)*132+d];
                float y0 = Xs[(c0+0)*132+d], y1 = Xs[(c0+1)*132+d], y2 = Xs[(c0+2)*132+d];
                acc[0][0] += x0*y0; acc[0][1] += x0*y1; acc[0][2] += x0*y2;
                acc[1][0] += x1*y0; acc[1][1] += x1*y1; acc[1][2] += x1*y2;
                acc[2][0] += x2*y0; acc[2][1] += x2*y1; acc[2][2] += x2*y2;
            }
        }
        __syncthreads();
    }
    if (act) {
        float* gp = g_gimg + (size_t)i * (RR * RR);
        #pragma unroll
        for (int a = 0; a < 3; a++)
            #pragma unroll
            for (int b = 0; b < 3; b++)
                gp[(r0 + a) * RR + (c0 + b)] = acc[a][b];
    }
}

// ============================================================
// Kernel 3: per-caption 32x32 word Gram
// ============================================================
__global__ __launch_bounds__(256) void gram_cap_kernel(const float* __restrict__ X) {
    __shared__ float Xs[32 * 132];
    const int c = blockIdx.x, tid = threadIdx.x;
    float acc[4][4];
    #pragma unroll
    for (int a = 0; a < 4; a++)
        #pragma unroll
        for (int b = 0; b < 4; b++) acc[a][b] = 0.f;
    const int r0 = (tid / 8) * 4, c0 = (tid % 8) * 4;
    const bool act = tid < 64;
    const float* base = X + (size_t)c * WW * DD;
    for (int ch = 0; ch < 8; ch++) {
        for (int f = tid; f < 1024; f += 256) {
            int row = f >> 5, q = f & 31;
            float4 v = *(const float4*)(base + (size_t)row * DD + ch * 128 + q * 4);
            *(float4*)&Xs[row * 132 + q * 4] = v;
        }
        __syncthreads();
        if (act) {
            for (int d = 0; d < 128; d++) {
                float x0 = Xs[(r0+0)*132+d], x1 = Xs[(r0+1)*132+d];
                float x2 = Xs[(r0+2)*132+d], x3 = Xs[(r0+3)*132+d];
                float y0 = Xs[(c0+0)*132+d], y1 = Xs[(c0+1)*132+d];
                float y2 = Xs[(c0+2)*132+d], y3 = Xs[(c0+3)*132+d];
                acc[0][0]+=x0*y0; acc[0][1]+=x0*y1; acc[0][2]+=x0*y2; acc[0][3]+=x0*y3;
                acc[1][0]+=x1*y0; acc[1][1]+=x1*y1; acc[1][2]+=x1*y2; acc[1][3]+=x1*y3;
                acc[2][0]+=x2*y0; acc[2][1]+=x2*y1; acc[2][2]+=x2*y2; acc[2][3]+=x2*y3;
                acc[3][0]+=x3*y0; acc[3][1]+=x3*y1; acc[3][2]+=x3*y2; acc[3][3]+=x3*y3;
            }
        }
        __syncthreads();
    }
    if (act) {
        float* gp = g_gcap + (size_t)c * (WW * WW);
        #pragma unroll
        for (int a = 0; a < 4; a++)
            #pragma unroll
            for (int b = 0; b < 4; b++)
                gp[(r0 + a) * WW + (c0 + b)] = acc[a][b];
    }
}

// ============================================================
// Kernel 4: per-(image,caption) focal attention + cosine
// ============================================================
__global__ __launch_bounds__(256) void pair_kernel(float* __restrict__ out) {
    const int i = blockIdx.x, c = blockIdx.y;
    __shared__ float M[36 * 33];
    __shared__ float A1[36 * 33];
    __shared__ float A2[32 * 37];
    __shared__ float Gi[36 * 37];
    __shared__ float Gc[32 * 33];
    __shared__ float At[32 * 37];
    __shared__ float Ai[36 * 33];
    __shared__ float accT, accI;

    const int tid = threadIdx.x;
    if (tid == 0) { accT = 0.f; accI = 0.f; }

    const float* simp = g_sim + ((size_t)c * NI + i) * (RR * WW);
    for (int g = tid; g < RR * WW; g += 256) {
        int r = g >> 5, w = g & 31;
        M[r * 33 + w] = simp[g];
    }
    const float* gip = g_gimg + (size_t)i * (RR * RR);
    for (int g = tid; g < RR * RR; g += 256) {
        int r = g / 36, rr = g % 36;
        Gi[r * 37 + rr] = gip[g];
    }
    const float* gcp = g_gcap + (size_t)c * (WW * WW);
    for (int g = tid; g < WW * WW; g += 256) {
        int w = g >> 5, ww = g & 31;
        Gc[w * 33 + ww] = gcp[g];
    }
    __syncthreads();

    const int wd = tid >> 5, ln = tid & 31;

    for (int task = wd; task < 68; task += 8) {
        if (task < 36) {
            int r = task;
            float v = M[r * 33 + ln];
            v = v > 0.f ? v : 0.1f * v;
            float nrm = sqrtf(wsum(v * v)) + 1e-8f;
            A1[r * 33 + ln] = v / nrm;
        } else {
            int w = task - 36;
            float v1 = M[ln * 33 + w];
            v1 = v1 > 0.f ? v1 : 0.1f * v1;
            float v2 = 0.f;
            if (ln < 4) {
                v2 = M[(ln + 32) * 33 + w];
                v2 = v2 > 0.f ? v2 : 0.1f * v2;
            }
            float nrm = sqrtf(wsum(v1 * v1 + v2 * v2)) + 1e-8f;
            A2[w * 37 + ln] = v1 / nrm;
            if (ln < 4) A2[w * 37 + ln + 32] = v2 / nrm;
        }
    }
    __syncthreads();

    for (int task = wd; task < 68; task += 8) {
        if (task < 32) {
            int w = task;
            int r1 = ln, r2 = ln + 32;
            bool has2 = ln < 4;
            float v1 = A1[r1 * 33 + w];
            float v2 = has2 ? A1[r2 * 33 + w] : 0.f;
            float x1 = 20.f * v1;
            float x2 = has2 ? 20.f * v2 : -1e30f;
            float mx = wmax(fmaxf(x1, x2));
            float e1 = __expf(x1 - mx);
            float e2 = has2 ? __expf(x2 - mx) : 0.f;
            float s = wsum(e1 + e2);
            float p1 = e1 / s, p2 = e2 / s;
            bool m1 = (p1 * 36.f - 1.f) > 0.f;
            bool m2 = has2 && ((p2 * 36.f - 1.f) > 0.f);
            float t = wsum((m1 ? p1 : 0.f) + (m2 ? p2 : 0.f));
            float at1 = m1 ? p1 / t : 0.f;
            float at2 = m2 ? p2 / t : 0.f;
            float num = wsum(at1 * M[r1 * 33 + w] + (has2 ? at2 * M[r2 * 33 + w] : 0.f));
            At[w * 37 + r1] = at1;
            if (has2) At[w * 37 + r2] = at2;
            __syncwarp();
            float in1 = 0.f, in2 = 0.f;
            const float* atp = &At[w * 37];
            #pragma unroll 4
            for (int rr = 0; rr < 36; rr++) {
                float a = atp[rr];
                in1 = fmaf(Gi[r1 * 37 + rr], a, in1);
                if (has2) in2 = fmaf(Gi[r2 * 37 + rr], a, in2);
            }
            float d2 = wsum(at1 * in1 + at2 * in2);
            float den = fmaxf(sqrtf(d2), 1e-8f);
            float ncap = fmaxf(sqrtf(Gc[w * 33 + w]), 1e-8f);
            float cs = num / (ncap * den);
            if (ln == 0) atomicAdd(&accT, cs);
        } else {
            int r = task - 32;
            float v = A2[ln * 37 + r];
            float x = 20.f * v;
            float mx = wmax(x);
            float e = __expf(x - mx);
            float s = wsum(e);
            float p = e / s;
            bool mk = (p * 32.f - 1.f) > 0.f;
            float t = wsum(mk ? p : 0.f);
            float at = mk ? p / t : 0.f;
            float num = wsum(at * M[r * 33 + ln]);
            Ai[r * 33 + ln] = at;
            __syncwarp();
            float inn = 0.f;
            const float* aip = &Ai[r * 33];
            #pragma unroll 4
            for (int ww2 = 0; ww2 < 32; ww2++) {
                inn = fmaf(Gc[ln * 33 + ww2], aip[ww2], inn);
            }
            float d2 = wsum(at * inn);
            float den = fmaxf(sqrtf(d2), 1e-8f);
            float nim = fmaxf(sqrtf(Gi[r * 37 + r]), 1e-8f);
            float cs = num / (nim * den);
            if (ln == 0) atomicAdd(&accI, cs);
        }
    }
    __syncthreads();
    if (tid == 0) out[(size_t)i * NC + c] = accT * (1.f / 32.f) + accI * (1.f / 36.f);
}

// ============================================================
extern "C" void kernel_launch(void* const* d_in, const int* in_sizes, int n_in,
                              void* d_out, int out_size) {
    const float* images   = (const float*)d_in[0];
    const float* captions = (const float*)d_in[1];
    float* out = (float*)d_out;

    const int SMEM_TOTAL = 2 * STAGE_B;   // 128 KB
    cudaFuncSetAttribute(gemm_mma, cudaFuncAttributeMaxDynamicSharedMemorySize, SMEM_TOTAL);

    const size_t n4 = ((size_t)MROWS * DD + (size_t)NCOLS * DD) / 4;
    convert_kernel<<<(unsigned)((n4 + 255) / 256), 256>>>(images, captions);
    gemm_mma<<<dim3(32, 36), 256, SMEM_TOTAL>>>();
    gram_img_kernel<<<128, 256>>>(images);
    gram_cap_kernel<<<128, 256>>>(captions);
    pair_kernel<<<dim3(128, 128), 256>>>(out);
}